// round 15
// baseline (speedup 1.0000x reference)
#include <cuda_runtime.h>
#include <cuda_fp16.h>
#include <mma.h>
#include <math.h>
#include <cstdint>

using namespace nvcuda;

#define Bsz   1024
#define Wsz   6
#define Dsz   512
#define Vsz   50257
#define Ksz   3072          // W*D
#define NSTEP 16

#define CUBIC_GAIN 0.032f
#define LAM   0.1f
#define SIG   0.5f
#define EPSN  1e-8f
#define ASYM_STR 1.25f
#define LN_EPS 1e-5f

// device-global scratch (no allocation allowed)
__device__ __align__(16) float  g_S[Bsz * Wsz * Dsz];
__device__ __align__(16) __half g_Th[Bsz * Wsz * Dsz];      // fp16 drift buffer
__device__ __align__(16) __half g_Sh[Bsz * Wsz * Dsz];      // fp16 mirror of S
__device__ __align__(16) __half g_Dh[Dsz * Dsz];            // fp16 diffusion
__device__ __align__(16) __half g_Bh[(size_t)Vsz * Ksz];    // fp16 readout

__device__ __forceinline__ float softplusf(float x) {
    return x > 0.f ? x + log1pf(expf(-x)) : log1pf(expf(x));
}

__device__ __forceinline__ void cp_async16h(__half* smem_dst, const __half* gmem_src,
                                            bool valid) {
    unsigned int saddr = (unsigned int)__cvta_generic_to_shared(smem_dst);
    int sz = valid ? 16 : 0;
    asm volatile("cp.async.ca.shared.global [%0], [%1], 16, %2;\n"
                 :: "r"(saddr), "l"(gmem_src), "r"(sz));
}

// ---------------------------------------------------------------------------
// gather + LayerNorm (writes fp32 state + fp16 mirror)
// ---------------------------------------------------------------------------
__global__ void gather_ln_kernel(const int* __restrict__ tokens,
                                 const float* __restrict__ embed) {
    int row = blockIdx.x;
    int tok = tokens[row];
    const float4* src = reinterpret_cast<const float4*>(embed + (size_t)tok * Dsz);
    float4 v = src[threadIdx.x];

    float s  = v.x + v.y + v.z + v.w;
    float sq = v.x * v.x + v.y * v.y + v.z * v.z + v.w * v.w;

    __shared__ float sh_s[4], sh_q[4];
    #pragma unroll
    for (int o = 16; o > 0; o >>= 1) {
        s  += __shfl_down_sync(0xFFFFFFFFu, s, o);
        sq += __shfl_down_sync(0xFFFFFFFFu, sq, o);
    }
    int wid = threadIdx.x >> 5, lane = threadIdx.x & 31;
    if (lane == 0) { sh_s[wid] = s; sh_q[wid] = sq; }
    __syncthreads();
    float fs = sh_s[0] + sh_s[1] + sh_s[2] + sh_s[3];
    float fq = sh_q[0] + sh_q[1] + sh_q[2] + sh_q[3];
    float mu  = fs * (1.f / Dsz);
    float var = fq * (1.f / Dsz) - mu * mu;
    float rstd = rsqrtf(var + LN_EPS);

    float4 o;
    o.x = (v.x - mu) * rstd;
    o.y = (v.y - mu) * rstd;
    o.z = (v.z - mu) * rstd;
    o.w = (v.w - mu) * rstd;
    reinterpret_cast<float4*>(g_S + (size_t)row * Dsz)[threadIdx.x] = o;

    __half2* hrow = reinterpret_cast<__half2*>(g_Sh + (size_t)row * Dsz);
    hrow[threadIdx.x * 2 + 0] = __floats2half2_rn(o.x, o.y);
    hrow[threadIdx.x * 2 + 1] = __floats2half2_rn(o.z, o.w);
}

// ---------------------------------------------------------------------------
// fp32 -> fp16 converters
// ---------------------------------------------------------------------------
__global__ void conv_w_kernel(const float* __restrict__ w) {
    size_t n4 = (size_t)Vsz * Ksz / 4;
    const float4* in = reinterpret_cast<const float4*>(w);
    uint2* o = reinterpret_cast<uint2*>(g_Bh);
    for (size_t i = (size_t)blockIdx.x * blockDim.x + threadIdx.x; i < n4;
         i += (size_t)gridDim.x * blockDim.x) {
        float4 v = in[i];
        __half2 lo = __floats2half2_rn(v.x, v.y);
        __half2 hi = __floats2half2_rn(v.z, v.w);
        uint2 pk;
        pk.x = *reinterpret_cast<unsigned*>(&lo);
        pk.y = *reinterpret_cast<unsigned*>(&hi);
        o[i] = pk;
    }
}

__global__ void conv_d_kernel(const float* __restrict__ dmat) {
    size_t n2 = (size_t)Dsz * Dsz / 2;
    const float2* in = reinterpret_cast<const float2*>(dmat);
    __half2* o = reinterpret_cast<__half2*>(g_Dh);
    for (size_t i = (size_t)blockIdx.x * blockDim.x + threadIdx.x; i < n2;
         i += (size_t)gridDim.x * blockDim.x)
        o[i] = __float22half2_rn(in[i]);
}

// ---------------------------------------------------------------------------
// STEP GEMM: 64x64x64 tiles, 128 threads, 2-stage, 5 CTAs/SM (proven R9
// mainloop), fp16 output via per-warp smem staging.
// ---------------------------------------------------------------------------
#define SBM 64
#define SBN 64
#define SBK 64
#define SLDS (SBK + 8)
#define S_SMEM_BYTES (2 * (SBM + SBN) * SLDS * 2)   // 36864

__global__ __launch_bounds__(128, 5)
void gemm_step(const __half* __restrict__ A, const __half* __restrict__ Bmat,
               __half* __restrict__ C, int M, int N, int K) {
    extern __shared__ __half smh[];
    __half* As = smh;
    __half* Bs = smh + 2 * SBM * SLDS;

    const int m0 = blockIdx.x * SBM;
    const int n0 = blockIdx.y * SBN;
    const int tid = threadIdx.x;
    const int warp = tid >> 5, lane = tid & 31;
    const int wm = warp >> 1;
    const int wn = warp & 1;
    const int r_ld = tid >> 3;
    const int c_ld = (tid & 7) * 8;

    wmma::fragment<wmma::accumulator, 16, 16, 16, float> acc[2][2];
    #pragma unroll
    for (int mi = 0; mi < 2; mi++)
        #pragma unroll
        for (int ni = 0; ni < 2; ni++)
            wmma::fill_fragment(acc[mi][ni], 0.0f);

    const int niter = K / SBK;

    auto load_stage = [&](int st, int k0) {
        __half* as = As + st * SBM * SLDS;
        __half* bs = Bs + st * SBN * SLDS;
        #pragma unroll
        for (int t = 0; t < 4; t++) {
            int r = r_ld + t * 16;
            cp_async16h(as + r * SLDS + c_ld,
                        A + (size_t)(m0 + r) * K + k0 + c_ld, true);
        }
        #pragma unroll
        for (int t = 0; t < 4; t++) {
            int r = r_ld + t * 16;
            cp_async16h(bs + r * SLDS + c_ld,
                        Bmat + (size_t)(n0 + r) * K + k0 + c_ld, true);
        }
        asm volatile("cp.async.commit_group;\n" ::: "memory");
    };

    load_stage(0, 0);

    for (int i = 0; i < niter; i++) {
        if (i + 1 < niter) {
            load_stage((i + 1) & 1, (i + 1) * SBK);
            asm volatile("cp.async.wait_group 1;\n" ::: "memory");
        } else {
            asm volatile("cp.async.wait_group 0;\n" ::: "memory");
        }
        __syncthreads();

        const int st = i & 1;
        const __half* as = As + st * SBM * SLDS;
        const __half* bs = Bs + st * SBN * SLDS;

        #pragma unroll
        for (int ks = 0; ks < SBK; ks += 16) {
            wmma::fragment<wmma::matrix_a, 16, 16, 16, __half,
                           wmma::row_major> af[2];
            wmma::fragment<wmma::matrix_b, 16, 16, 16, __half,
                           wmma::col_major> bf[2];
            #pragma unroll
            for (int mi = 0; mi < 2; mi++)
                wmma::load_matrix_sync(af[mi],
                    as + (size_t)(wm * 32 + mi * 16) * SLDS + ks, SLDS);
            #pragma unroll
            for (int ni = 0; ni < 2; ni++)
                wmma::load_matrix_sync(bf[ni],
                    bs + (size_t)(wn * 32 + ni * 16) * SLDS + ks, SLDS);
            #pragma unroll
            for (int mi = 0; mi < 2; mi++)
                #pragma unroll
                for (int ni = 0; ni < 2; ni++)
                    wmma::mma_sync(acc[mi][ni], af[mi], bf[ni], acc[mi][ni]);
        }
        __syncthreads();
    }

    // fp16 store via per-warp smem staging: warp owns a 32x36 float region
    // (4608 B x 4 warps = 18432 B, reuses pipeline smem; disjoint per warp).
    float* wbuf = reinterpret_cast<float*>(smh) + warp * (32 * 36);
    #pragma unroll
    for (int mi = 0; mi < 2; mi++)
        #pragma unroll
        for (int ni = 0; ni < 2; ni++)
            wmma::store_matrix_sync(wbuf + (mi * 16) * 36 + ni * 16,
                                    acc[mi][ni], 36, wmma::mem_row_major);
    __syncwarp();
    {
        const float* rowp = wbuf + lane * 36;
        uint2 pk[4];
        #pragma unroll
        for (int q = 0; q < 4; q++) {
            __half2 h0 = __floats2half2_rn(rowp[q * 8 + 0], rowp[q * 8 + 1]);
            __half2 h1 = __floats2half2_rn(rowp[q * 8 + 2], rowp[q * 8 + 3]);
            __half2 h2 = __floats2half2_rn(rowp[q * 8 + 4], rowp[q * 8 + 5]);
            __half2 h3 = __floats2half2_rn(rowp[q * 8 + 6], rowp[q * 8 + 7]);
            pk[q].x = *reinterpret_cast<unsigned*>(&h0);
            pk[q].y = *reinterpret_cast<unsigned*>(&h1);
            uint2 t;
            t.x = *reinterpret_cast<unsigned*>(&h2);
            t.y = *reinterpret_cast<unsigned*>(&h3);
            uint4 full;
            full.x = pk[q].x; full.y = pk[q].y; full.z = t.x; full.w = t.y;
            *reinterpret_cast<uint4*>(
                C + (size_t)(m0 + wm * 32 + lane) * N + n0 + wn * 32 + q * 8) = full;
        }
    }
}

// ---------------------------------------------------------------------------
// FINAL GEMM: 128x128x64, 128 threads, 4 warps (2x2, warp tile 64x64),
// 2-stage cp.async (proven R12 mainloop). Coalesced epilogue: full-tile
// smem staging (128 x 132 floats = 67584 B <= 73728) then column-owned
// row-burst stores (512 B coalesced per row).
// ---------------------------------------------------------------------------
#define GBM 128
#define GBN 128
#define GBK 64
#define GLDS (GBK + 8)                     // 72 halves (144 B) per row
#define GSTG_HALVES ((GBM + GBN) * GLDS)
#define GEMM_SMEM_BYTES (2 * GSTG_HALVES * 2)   // 73728
#define ELD 132                             // epilogue ld (floats)

__global__ __launch_bounds__(128, 2)
void gemm_h(const __half* __restrict__ A, const __half* __restrict__ Bmat,
            float* __restrict__ C, int M, int N, int K) {
    extern __shared__ __half smh[];

    const int m0 = blockIdx.x * GBM;
    const int n0 = blockIdx.y * GBN;
    const int tid = threadIdx.x;
    const int warp = tid >> 5;
    const int wm = warp >> 1;            // 0..1 (64-row half)
    const int wn = warp & 1;             // 0..1 (64-col half)
    const int r_ld = tid >> 3;           // 0..15
    const int c_ld = (tid & 7) * 8;      // 0..56 halves

    wmma::fragment<wmma::accumulator, 16, 16, 16, float> acc[4][4];
    #pragma unroll
    for (int mi = 0; mi < 4; mi++)
        #pragma unroll
        for (int ni = 0; ni < 4; ni++)
            wmma::fill_fragment(acc[mi][ni], 0.0f);

    const int niter = K / GBK;      // 48

    auto load_stage = [&](int st, int k0) {
        __half* as = smh + st * GSTG_HALVES;
        __half* bs = as + GBM * GLDS;
        #pragma unroll
        for (int t = 0; t < 8; t++) {
            int r = r_ld + t * 16;
            cp_async16h(as + r * GLDS + c_ld,
                        A + (size_t)(m0 + r) * K + k0 + c_ld, true);
        }
        #pragma unroll
        for (int t = 0; t < 8; t++) {
            int r = r_ld + t * 16;
            int n = n0 + r;
            bool v = (n < N);
            cp_async16h(bs + r * GLDS + c_ld,
                        Bmat + (size_t)(v ? n : 0) * K + k0 + c_ld, v);
        }
        asm volatile("cp.async.commit_group;\n" ::: "memory");
    };

    load_stage(0, 0);

    for (int i = 0; i < niter; i++) {
        if (i + 1 < niter) {
            load_stage((i + 1) & 1, (i + 1) * GBK);
            asm volatile("cp.async.wait_group 1;\n" ::: "memory");
        } else {
            asm volatile("cp.async.wait_group 0;\n" ::: "memory");
        }
        __syncthreads();

        const int st = i & 1;
        const __half* as = smh + st * GSTG_HALVES;
        const __half* bs = as + GBM * GLDS;

        #pragma unroll
        for (int ks = 0; ks < GBK; ks += 16) {
            wmma::fragment<wmma::matrix_a, 16, 16, 16, __half,
                           wmma::row_major> af[4];
            wmma::fragment<wmma::matrix_b, 16, 16, 16, __half,
                           wmma::col_major> bf[4];
            #pragma unroll
            for (int mi = 0; mi < 4; mi++)
                wmma::load_matrix_sync(af[mi],
                    as + (size_t)(wm * 64 + mi * 16) * GLDS + ks, GLDS);
            #pragma unroll
            for (int ni = 0; ni < 4; ni++)
                wmma::load_matrix_sync(bf[ni],
                    bs + (size_t)(wn * 64 + ni * 16) * GLDS + ks, GLDS);
            #pragma unroll
            for (int mi = 0; mi < 4; mi++)
                #pragma unroll
                for (int ni = 0; ni < 4; ni++)
                    wmma::mma_sync(acc[mi][ni], af[mi], bf[ni], acc[mi][ni]);
        }
        __syncthreads();
    }

    // coalesced epilogue: fragments -> full-tile smem -> column-owned stores
    float* ebuf = reinterpret_cast<float*>(smh);
    #pragma unroll
    for (int mi = 0; mi < 4; mi++)
        #pragma unroll
        for (int ni = 0; ni < 4; ni++)
            wmma::store_matrix_sync(
                ebuf + (size_t)(wm * 64 + mi * 16) * ELD + wn * 64 + ni * 16,
                acc[mi][ni], ELD, wmma::mem_row_major);
    __syncthreads();

    int n = n0 + tid;
    if (n < N) {
        #pragma unroll 4
        for (int r = 0; r < GBM; r++)
            C[(size_t)(m0 + r) * N + n] = ebuf[(size_t)r * ELD + tid];
    }
}

// ---------------------------------------------------------------------------
// fused update kernel (reads fp16 drift, writes fp32 state + fp16 mirror)
// ---------------------------------------------------------------------------
__device__ __forceinline__ void block_reduce6(float v[Wsz], float red[Wsz][16],
                                              int wid, int lane) {
    #pragma unroll
    for (int i = 0; i < Wsz; i++) {
        float x = v[i];
        #pragma unroll
        for (int o = 16; o > 0; o >>= 1)
            x += __shfl_down_sync(0xFFFFFFFFu, x, o);
        if (lane == 0) red[i][wid] = x;
    }
    __syncthreads();
    #pragma unroll
    for (int i = 0; i < Wsz; i++) {
        float t = 0.f;
        #pragma unroll
        for (int w = 0; w < 16; w++) t += red[i][w];
        v[i] = t;
    }
    __syncthreads();
}

__global__ __launch_bounds__(512)
void update_kernel(const float* __restrict__ beta_p,
                   const float* __restrict__ gamma_raw,
                   const float* __restrict__ scale_raw,
                   const float* __restrict__ dt_raw,
                   const float* __restrict__ asym_p) {
    int b = blockIdx.x;
    int d = threadIdx.x;
    int wid = d >> 5, lane = d & 31;

    __shared__ float Wsh[Wsz][Wsz];
    __shared__ float wsumsh[Wsz];
    __shared__ float red[Wsz][16];

    float gamma = softplusf(*gamma_raw);
    float scale = softplusf(*scale_raw);
    float dt    = softplusf(*dt_raw);
    float beta  = *beta_p;
    float ta    = tanhf(*asym_p);
    float coeff = beta * SIG * scale;

    if (d < Wsz * Wsz) {
        int i = d / Wsz, j = d % Wsz;
        float w = 0.f;
        if (i != j) {
            float ji = (float)(j - i);
            float sgn = (ji > 0.f) ? 1.f : -1.f;
            float af = fmaxf(1.f + ASYM_STR * ta * sgn, 0.2f);
            w = expf(-gamma * fabsf(ji)) * af * coeff;
        }
        Wsh[i][j] = w;
    }
    __syncthreads();
    if (d < Wsz) {
        float ws = 0.f;
        #pragma unroll
        for (int j = 0; j < Wsz; j++) ws += Wsh[d][j];
        wsumsh[d] = ws;
    }
    __syncthreads();

    size_t base = (size_t)b * Wsz * Dsz + d;
    float s_loc[Wsz], t_loc[Wsz];
    #pragma unroll
    for (int i = 0; i < Wsz; i++) {
        s_loc[i] = g_S[base + i * Dsz];
        t_loc[i] = __half2float(g_Th[base + i * Dsz]);
    }

    float mu[Wsz];
    #pragma unroll
    for (int i = 0; i < Wsz; i++) mu[i] = s_loc[i];
    block_reduce6(mu, red, wid, lane);
    #pragma unroll
    for (int i = 0; i < Wsz; i++) mu[i] *= (1.f / Dsz);

    float sn[Wsz], sq[Wsz];
    #pragma unroll
    for (int i = 0; i < Wsz; i++) {
        float sig = -wsumsh[i] * s_loc[i];
        #pragma unroll
        for (int j = 0; j < Wsz; j++)
            sig = fmaf(Wsh[i][j], s_loc[j], sig);
        float c = s_loc[i] - mu[i];
        float drift = t_loc[i] + CUBIC_GAIN * tanhf(c) + sig - LAM * s_loc[i];
        float v = fmaf(dt, drift, s_loc[i]);
        if (!isfinite(v)) v = 0.f;
        sn[i] = v;
        sq[i] = v * v;
    }

    block_reduce6(sq, red, wid, lane);

    #pragma unroll
    for (int i = 0; i < Wsz; i++) {
        float nrm = sqrtf(sq[i]);
        float o = sn[i] / (nrm + EPSN);
        o = fminf(fmaxf(o, -10.f), 10.f);
        g_S[base + i * Dsz]  = o;
        g_Sh[base + i * Dsz] = __float2half_rn(o);
    }
}

// ---------------------------------------------------------------------------
// launch: conv_w forked onto a side stream, overlapped with the step loop.
// ---------------------------------------------------------------------------
extern "C" void kernel_launch(void* const* d_in, const int* in_sizes, int n_in,
                              void* d_out, int out_size) {
    const int*   tokens    = (const int*)d_in[0];
    const float* embed     = (const float*)d_in[1];
    const float* diffusion = (const float*)d_in[2];
    const float* readout   = (const float*)d_in[3];
    const float* beta      = (const float*)d_in[4];
    const float* g_raw     = (const float*)d_in[5];
    const float* s_raw     = (const float*)d_in[6];
    const float* dtraw     = (const float*)d_in[7];
    const float* asym      = (const float*)d_in[8];
    float* out = (float*)d_out;

    cudaFuncSetAttribute(gemm_h,
                         cudaFuncAttributeMaxDynamicSharedMemorySize,
                         GEMM_SMEM_BYTES);
    cudaFuncSetAttribute(gemm_step,
                         cudaFuncAttributeMaxDynamicSharedMemorySize,
                         S_SMEM_BYTES);

    void* sh_p;  cudaGetSymbolAddress(&sh_p, g_Sh);
    void* dh_p;  cudaGetSymbolAddress(&dh_p, g_Dh);
    void* bh_p;  cudaGetSymbolAddress(&bh_p, g_Bh);
    void* t_p;   cudaGetSymbolAddress(&t_p,  g_Th);
    const __half* Sh = (const __half*)sh_p;
    const __half* Dh = (const __half*)dh_p;
    const __half* Bh = (const __half*)bh_p;
    __half* Tp = (__half*)t_p;

    cudaStream_t s2;
    cudaStreamCreateWithFlags(&s2, cudaStreamNonBlocking);
    cudaEvent_t eFork, eJoin;
    cudaEventCreateWithFlags(&eFork, cudaEventDisableTiming);
    cudaEventCreateWithFlags(&eJoin, cudaEventDisableTiming);

    cudaEventRecord(eFork, 0);
    cudaStreamWaitEvent(s2, eFork, 0);
    conv_w_kernel<<<8192, 256, 0, s2>>>(readout);
    cudaEventRecord(eJoin, s2);

    conv_d_kernel<<<256, 256>>>(diffusion);
    gather_ln_kernel<<<Bsz * Wsz, 128>>>(tokens, embed);

    for (int s = 0; s < NSTEP; s++) {
        gemm_step<<<dim3((Bsz * Wsz) / SBM, Dsz / SBN), 128, S_SMEM_BYTES>>>(
            Sh, Dh, Tp, Bsz * Wsz, Dsz, Dsz);
        update_kernel<<<Bsz, Dsz>>>(beta, g_raw, s_raw, dtraw, asym);
    }

    cudaStreamWaitEvent(0, eJoin, 0);

    // logits = S.reshape(1024, 3072) @ readout^T  (M=1024, N=50257, K=3072)
    gemm_h<<<dim3(Bsz / GBM, (Vsz + GBN - 1) / GBN), 128, GEMM_SMEM_BYTES>>>(
        Sh, Bh, out, Bsz, Vsz, Ksz);
}

// round 16
// speedup vs baseline: 1.0122x; 1.0122x over previous
#include <cuda_runtime.h>
#include <cuda_fp16.h>
#include <mma.h>
#include <math.h>
#include <cstdint>

using namespace nvcuda;

#define Bsz   1024
#define Wsz   6
#define Dsz   512
#define Vsz   50257
#define Ksz   3072          // W*D
#define NSTEP 16

#define CUBIC_GAIN 0.032f
#define LAM   0.1f
#define SIG   0.5f
#define EPSN  1e-8f
#define ASYM_STR 1.25f
#define LN_EPS 1e-5f

// device-global scratch (no allocation allowed)
__device__ __align__(16) float  g_S[Bsz * Wsz * Dsz];
__device__ __align__(16) float  g_T[Bsz * Wsz * Dsz];
__device__ __align__(16) __half g_Sh[Bsz * Wsz * Dsz];      // fp16 mirror of S
__device__ __align__(16) __half g_Dh[Dsz * Dsz];            // fp16 diffusion
__device__ __align__(16) __half g_Bh[(size_t)Vsz * Ksz];    // fp16 readout

__device__ __forceinline__ float softplusf(float x) {
    return x > 0.f ? x + log1pf(expf(-x)) : log1pf(expf(x));
}

__device__ __forceinline__ void cp_async16h(__half* smem_dst, const __half* gmem_src,
                                            bool valid) {
    unsigned int saddr = (unsigned int)__cvta_generic_to_shared(smem_dst);
    int sz = valid ? 16 : 0;
    asm volatile("cp.async.ca.shared.global [%0], [%1], 16, %2;\n"
                 :: "r"(saddr), "l"(gmem_src), "r"(sz));
}

// ---------------------------------------------------------------------------
// gather + LayerNorm (writes fp32 state + fp16 mirror)
// ---------------------------------------------------------------------------
__global__ void gather_ln_kernel(const int* __restrict__ tokens,
                                 const float* __restrict__ embed) {
    int row = blockIdx.x;
    int tok = tokens[row];
    const float4* src = reinterpret_cast<const float4*>(embed + (size_t)tok * Dsz);
    float4 v = src[threadIdx.x];

    float s  = v.x + v.y + v.z + v.w;
    float sq = v.x * v.x + v.y * v.y + v.z * v.z + v.w * v.w;

    __shared__ float sh_s[4], sh_q[4];
    #pragma unroll
    for (int o = 16; o > 0; o >>= 1) {
        s  += __shfl_down_sync(0xFFFFFFFFu, s, o);
        sq += __shfl_down_sync(0xFFFFFFFFu, sq, o);
    }
    int wid = threadIdx.x >> 5, lane = threadIdx.x & 31;
    if (lane == 0) { sh_s[wid] = s; sh_q[wid] = sq; }
    __syncthreads();
    float fs = sh_s[0] + sh_s[1] + sh_s[2] + sh_s[3];
    float fq = sh_q[0] + sh_q[1] + sh_q[2] + sh_q[3];
    float mu  = fs * (1.f / Dsz);
    float var = fq * (1.f / Dsz) - mu * mu;
    float rstd = rsqrtf(var + LN_EPS);

    float4 o;
    o.x = (v.x - mu) * rstd;
    o.y = (v.y - mu) * rstd;
    o.z = (v.z - mu) * rstd;
    o.w = (v.w - mu) * rstd;
    reinterpret_cast<float4*>(g_S + (size_t)row * Dsz)[threadIdx.x] = o;

    __half2* hrow = reinterpret_cast<__half2*>(g_Sh + (size_t)row * Dsz);
    hrow[threadIdx.x * 2 + 0] = __floats2half2_rn(o.x, o.y);
    hrow[threadIdx.x * 2 + 1] = __floats2half2_rn(o.z, o.w);
}

// ---------------------------------------------------------------------------
// fp32 -> fp16 converters
// ---------------------------------------------------------------------------
__global__ void conv_w_kernel(const float* __restrict__ w) {
    size_t n4 = (size_t)Vsz * Ksz / 4;
    const float4* in = reinterpret_cast<const float4*>(w);
    uint2* o = reinterpret_cast<uint2*>(g_Bh);
    for (size_t i = (size_t)blockIdx.x * blockDim.x + threadIdx.x; i < n4;
         i += (size_t)gridDim.x * blockDim.x) {
        float4 v = in[i];
        __half2 lo = __floats2half2_rn(v.x, v.y);
        __half2 hi = __floats2half2_rn(v.z, v.w);
        uint2 pk;
        pk.x = *reinterpret_cast<unsigned*>(&lo);
        pk.y = *reinterpret_cast<unsigned*>(&hi);
        o[i] = pk;
    }
}

__global__ void conv_d_kernel(const float* __restrict__ dmat) {
    size_t n2 = (size_t)Dsz * Dsz / 2;
    const float2* in = reinterpret_cast<const float2*>(dmat);
    __half2* o = reinterpret_cast<__half2*>(g_Dh);
    for (size_t i = (size_t)blockIdx.x * blockDim.x + threadIdx.x; i < n2;
         i += (size_t)gridDim.x * blockDim.x)
        o[i] = __float22half2_rn(in[i]);
}

// ---------------------------------------------------------------------------
// STEP GEMM (proven R9/R14): 64x64x64 tiles, 128 threads, 2-stage, 5 CTAs/SM,
// fp32 output via direct fragment stores.
// ---------------------------------------------------------------------------
#define SBM 64
#define SBN 64
#define SBK 64
#define SLDS (SBK + 8)
#define S_SMEM_BYTES (2 * (SBM + SBN) * SLDS * 2)   // 36864

__global__ __launch_bounds__(128, 5)
void gemm_step(const __half* __restrict__ A, const __half* __restrict__ Bmat,
               float* __restrict__ C, int M, int N, int K) {
    extern __shared__ __half smh[];
    __half* As = smh;
    __half* Bs = smh + 2 * SBM * SLDS;

    const int m0 = blockIdx.x * SBM;
    const int n0 = blockIdx.y * SBN;
    const int tid = threadIdx.x;
    const int warp = tid >> 5;
    const int wm = warp >> 1;
    const int wn = warp & 1;
    const int r_ld = tid >> 3;
    const int c_ld = (tid & 7) * 8;

    wmma::fragment<wmma::accumulator, 16, 16, 16, float> acc[2][2];
    #pragma unroll
    for (int mi = 0; mi < 2; mi++)
        #pragma unroll
        for (int ni = 0; ni < 2; ni++)
            wmma::fill_fragment(acc[mi][ni], 0.0f);

    const int niter = K / SBK;

    auto load_stage = [&](int st, int k0) {
        __half* as = As + st * SBM * SLDS;
        __half* bs = Bs + st * SBN * SLDS;
        #pragma unroll
        for (int t = 0; t < 4; t++) {
            int r = r_ld + t * 16;
            cp_async16h(as + r * SLDS + c_ld,
                        A + (size_t)(m0 + r) * K + k0 + c_ld, true);
        }
        #pragma unroll
        for (int t = 0; t < 4; t++) {
            int r = r_ld + t * 16;
            cp_async16h(bs + r * SLDS + c_ld,
                        Bmat + (size_t)(n0 + r) * K + k0 + c_ld, true);
        }
        asm volatile("cp.async.commit_group;\n" ::: "memory");
    };

    load_stage(0, 0);

    for (int i = 0; i < niter; i++) {
        if (i + 1 < niter) {
            load_stage((i + 1) & 1, (i + 1) * SBK);
            asm volatile("cp.async.wait_group 1;\n" ::: "memory");
        } else {
            asm volatile("cp.async.wait_group 0;\n" ::: "memory");
        }
        __syncthreads();

        const int st = i & 1;
        const __half* as = As + st * SBM * SLDS;
        const __half* bs = Bs + st * SBN * SLDS;

        #pragma unroll
        for (int ks = 0; ks < SBK; ks += 16) {
            wmma::fragment<wmma::matrix_a, 16, 16, 16, __half,
                           wmma::row_major> af[2];
            wmma::fragment<wmma::matrix_b, 16, 16, 16, __half,
                           wmma::col_major> bf[2];
            #pragma unroll
            for (int mi = 0; mi < 2; mi++)
                wmma::load_matrix_sync(af[mi],
                    as + (size_t)(wm * 32 + mi * 16) * SLDS + ks, SLDS);
            #pragma unroll
            for (int ni = 0; ni < 2; ni++)
                wmma::load_matrix_sync(bf[ni],
                    bs + (size_t)(wn * 32 + ni * 16) * SLDS + ks, SLDS);
            #pragma unroll
            for (int mi = 0; mi < 2; mi++)
                #pragma unroll
                for (int ni = 0; ni < 2; ni++)
                    wmma::mma_sync(acc[mi][ni], af[mi], bf[ni], acc[mi][ni]);
        }
        __syncthreads();
    }

    #pragma unroll
    for (int mi = 0; mi < 2; mi++)
        #pragma unroll
        for (int ni = 0; ni < 2; ni++) {
            size_t off = (size_t)(m0 + wm * 32 + mi * 16) * N
                       + (n0 + wn * 32 + ni * 16);
            wmma::store_matrix_sync(C + off, acc[mi][ni], N, wmma::mem_row_major);
        }
}

// ---------------------------------------------------------------------------
// FINAL GEMM: 128x128x64, 128 threads, 4 warps (2x2, warp tile 64x64),
// 2-stage cp.async (proven R12 mainloop). Coalesced epilogue: full-tile
// smem staging (128 x 132 floats = 67584 B <= 73728) then column-owned
// row-burst stores (512 B coalesced per row).
// ---------------------------------------------------------------------------
#define GBM 128
#define GBN 128
#define GBK 64
#define GLDS (GBK + 8)                     // 72 halves (144 B) per row
#define GSTG_HALVES ((GBM + GBN) * GLDS)
#define GEMM_SMEM_BYTES (2 * GSTG_HALVES * 2)   // 73728
#define ELD 132                             // epilogue ld (floats)

__global__ __launch_bounds__(128, 2)
void gemm_h(const __half* __restrict__ A, const __half* __restrict__ Bmat,
            float* __restrict__ C, int M, int N, int K) {
    extern __shared__ __half smh[];

    const int m0 = blockIdx.x * GBM;
    const int n0 = blockIdx.y * GBN;
    const int tid = threadIdx.x;
    const int warp = tid >> 5;
    const int wm = warp >> 1;            // 0..1 (64-row half)
    const int wn = warp & 1;             // 0..1 (64-col half)
    const int r_ld = tid >> 3;           // 0..15
    const int c_ld = (tid & 7) * 8;      // 0..56 halves

    wmma::fragment<wmma::accumulator, 16, 16, 16, float> acc[4][4];
    #pragma unroll
    for (int mi = 0; mi < 4; mi++)
        #pragma unroll
        for (int ni = 0; ni < 4; ni++)
            wmma::fill_fragment(acc[mi][ni], 0.0f);

    const int niter = K / GBK;      // 48

    auto load_stage = [&](int st, int k0) {
        __half* as = smh + st * GSTG_HALVES;
        __half* bs = as + GBM * GLDS;
        #pragma unroll
        for (int t = 0; t < 8; t++) {
            int r = r_ld + t * 16;
            cp_async16h(as + r * GLDS + c_ld,
                        A + (size_t)(m0 + r) * K + k0 + c_ld, true);
        }
        #pragma unroll
        for (int t = 0; t < 8; t++) {
            int r = r_ld + t * 16;
            int n = n0 + r;
            bool v = (n < N);
            cp_async16h(bs + r * GLDS + c_ld,
                        Bmat + (size_t)(v ? n : 0) * K + k0 + c_ld, v);
        }
        asm volatile("cp.async.commit_group;\n" ::: "memory");
    };

    load_stage(0, 0);

    for (int i = 0; i < niter; i++) {
        if (i + 1 < niter) {
            load_stage((i + 1) & 1, (i + 1) * GBK);
            asm volatile("cp.async.wait_group 1;\n" ::: "memory");
        } else {
            asm volatile("cp.async.wait_group 0;\n" ::: "memory");
        }
        __syncthreads();

        const int st = i & 1;
        const __half* as = smh + st * GSTG_HALVES;
        const __half* bs = as + GBM * GLDS;

        #pragma unroll
        for (int ks = 0; ks < GBK; ks += 16) {
            wmma::fragment<wmma::matrix_a, 16, 16, 16, __half,
                           wmma::row_major> af[4];
            wmma::fragment<wmma::matrix_b, 16, 16, 16, __half,
                           wmma::col_major> bf[4];
            #pragma unroll
            for (int mi = 0; mi < 4; mi++)
                wmma::load_matrix_sync(af[mi],
                    as + (size_t)(wm * 64 + mi * 16) * GLDS + ks, GLDS);
            #pragma unroll
            for (int ni = 0; ni < 4; ni++)
                wmma::load_matrix_sync(bf[ni],
                    bs + (size_t)(wn * 64 + ni * 16) * GLDS + ks, GLDS);
            #pragma unroll
            for (int mi = 0; mi < 4; mi++)
                #pragma unroll
                for (int ni = 0; ni < 4; ni++)
                    wmma::mma_sync(acc[mi][ni], af[mi], bf[ni], acc[mi][ni]);
        }
        __syncthreads();
    }

    // coalesced epilogue: fragments -> full-tile smem -> column-owned stores
    float* ebuf = reinterpret_cast<float*>(smh);
    #pragma unroll
    for (int mi = 0; mi < 4; mi++)
        #pragma unroll
        for (int ni = 0; ni < 4; ni++)
            wmma::store_matrix_sync(
                ebuf + (size_t)(wm * 64 + mi * 16) * ELD + wn * 64 + ni * 16,
                acc[mi][ni], ELD, wmma::mem_row_major);
    __syncthreads();

    int n = n0 + tid;
    if (n < N) {
        #pragma unroll 4
        for (int r = 0; r < GBM; r++)
            C[(size_t)(m0 + r) * N + n] = ebuf[(size_t)r * ELD + tid];
    }
}

// ---------------------------------------------------------------------------
// fused update kernel (reads fp32 drift, writes fp32 state + fp16 mirror)
// ---------------------------------------------------------------------------
__device__ __forceinline__ void block_reduce6(float v[Wsz], float red[Wsz][16],
                                              int wid, int lane) {
    #pragma unroll
    for (int i = 0; i < Wsz; i++) {
        float x = v[i];
        #pragma unroll
        for (int o = 16; o > 0; o >>= 1)
            x += __shfl_down_sync(0xFFFFFFFFu, x, o);
        if (lane == 0) red[i][wid] = x;
    }
    __syncthreads();
    #pragma unroll
    for (int i = 0; i < Wsz; i++) {
        float t = 0.f;
        #pragma unroll
        for (int w = 0; w < 16; w++) t += red[i][w];
        v[i] = t;
    }
    __syncthreads();
}

__global__ __launch_bounds__(512)
void update_kernel(const float* __restrict__ beta_p,
                   const float* __restrict__ gamma_raw,
                   const float* __restrict__ scale_raw,
                   const float* __restrict__ dt_raw,
                   const float* __restrict__ asym_p) {
    int b = blockIdx.x;
    int d = threadIdx.x;
    int wid = d >> 5, lane = d & 31;

    __shared__ float Wsh[Wsz][Wsz];
    __shared__ float wsumsh[Wsz];
    __shared__ float red[Wsz][16];

    float gamma = softplusf(*gamma_raw);
    float scale = softplusf(*scale_raw);
    float dt    = softplusf(*dt_raw);
    float beta  = *beta_p;
    float ta    = tanhf(*asym_p);
    float coeff = beta * SIG * scale;

    if (d < Wsz * Wsz) {
        int i = d / Wsz, j = d % Wsz;
        float w = 0.f;
        if (i != j) {
            float ji = (float)(j - i);
            float sgn = (ji > 0.f) ? 1.f : -1.f;
            float af = fmaxf(1.f + ASYM_STR * ta * sgn, 0.2f);
            w = expf(-gamma * fabsf(ji)) * af * coeff;
        }
        Wsh[i][j] = w;
    }
    __syncthreads();
    if (d < Wsz) {
        float ws = 0.f;
        #pragma unroll
        for (int j = 0; j < Wsz; j++) ws += Wsh[d][j];
        wsumsh[d] = ws;
    }
    __syncthreads();

    size_t base = (size_t)b * Wsz * Dsz + d;
    float s_loc[Wsz], t_loc[Wsz];
    #pragma unroll
    for (int i = 0; i < Wsz; i++) {
        s_loc[i] = g_S[base + i * Dsz];
        t_loc[i] = g_T[base + i * Dsz];
    }

    float mu[Wsz];
    #pragma unroll
    for (int i = 0; i < Wsz; i++) mu[i] = s_loc[i];
    block_reduce6(mu, red, wid, lane);
    #pragma unroll
    for (int i = 0; i < Wsz; i++) mu[i] *= (1.f / Dsz);

    float sn[Wsz], sq[Wsz];
    #pragma unroll
    for (int i = 0; i < Wsz; i++) {
        float sig = -wsumsh[i] * s_loc[i];
        #pragma unroll
        for (int j = 0; j < Wsz; j++)
            sig = fmaf(Wsh[i][j], s_loc[j], sig);
        float c = s_loc[i] - mu[i];
        float drift = t_loc[i] + CUBIC_GAIN * tanhf(c) + sig - LAM * s_loc[i];
        float v = fmaf(dt, drift, s_loc[i]);
        if (!isfinite(v)) v = 0.f;
        sn[i] = v;
        sq[i] = v * v;
    }

    block_reduce6(sq, red, wid, lane);

    #pragma unroll
    for (int i = 0; i < Wsz; i++) {
        float nrm = sqrtf(sq[i]);
        float o = sn[i] / (nrm + EPSN);
        o = fminf(fmaxf(o, -10.f), 10.f);
        g_S[base + i * Dsz]  = o;
        g_Sh[base + i * Dsz] = __float2half_rn(o);
    }
}

// ---------------------------------------------------------------------------
// launch: conv_w forked onto a side stream, overlapped with the step loop.
// ---------------------------------------------------------------------------
extern "C" void kernel_launch(void* const* d_in, const int* in_sizes, int n_in,
                              void* d_out, int out_size) {
    const int*   tokens    = (const int*)d_in[0];
    const float* embed     = (const float*)d_in[1];
    const float* diffusion = (const float*)d_in[2];
    const float* readout   = (const float*)d_in[3];
    const float* beta      = (const float*)d_in[4];
    const float* g_raw     = (const float*)d_in[5];
    const float* s_raw     = (const float*)d_in[6];
    const float* dtraw     = (const float*)d_in[7];
    const float* asym      = (const float*)d_in[8];
    float* out = (float*)d_out;

    cudaFuncSetAttribute(gemm_h,
                         cudaFuncAttributeMaxDynamicSharedMemorySize,
                         GEMM_SMEM_BYTES);
    cudaFuncSetAttribute(gemm_step,
                         cudaFuncAttributeMaxDynamicSharedMemorySize,
                         S_SMEM_BYTES);

    void* sh_p;  cudaGetSymbolAddress(&sh_p, g_Sh);
    void* dh_p;  cudaGetSymbolAddress(&dh_p, g_Dh);
    void* bh_p;  cudaGetSymbolAddress(&bh_p, g_Bh);
    void* t_p;   cudaGetSymbolAddress(&t_p,  g_T);
    const __half* Sh = (const __half*)sh_p;
    const __half* Dh = (const __half*)dh_p;
    const __half* Bh = (const __half*)bh_p;
    float* Tp = (float*)t_p;

    cudaStream_t s2;
    cudaStreamCreateWithFlags(&s2, cudaStreamNonBlocking);
    cudaEvent_t eFork, eJoin;
    cudaEventCreateWithFlags(&eFork, cudaEventDisableTiming);
    cudaEventCreateWithFlags(&eJoin, cudaEventDisableTiming);

    cudaEventRecord(eFork, 0);
    cudaStreamWaitEvent(s2, eFork, 0);
    conv_w_kernel<<<8192, 256, 0, s2>>>(readout);
    cudaEventRecord(eJoin, s2);

    conv_d_kernel<<<256, 256>>>(diffusion);
    gather_ln_kernel<<<Bsz * Wsz, 128>>>(tokens, embed);

    for (int s = 0; s < NSTEP; s++) {
        gemm_step<<<dim3((Bsz * Wsz) / SBM, Dsz / SBN), 128, S_SMEM_BYTES>>>(
            Sh, Dh, Tp, Bsz * Wsz, Dsz, Dsz);
        update_kernel<<<Bsz, Dsz>>>(beta, g_raw, s_raw, dtraw, asym);
    }

    cudaStreamWaitEvent(0, eJoin, 0);

    // logits = S.reshape(1024, 3072) @ readout^T  (M=1024, N=50257, K=3072)
    gemm_h<<<dim3(Bsz / GBM, (Vsz + GBN - 1) / GBN), 128, GEMM_SMEM_BYTES>>>(
        Sh, Bh, out, Bsz, Vsz, Ksz);
}

// round 17
// speedup vs baseline: 1.0234x; 1.0111x over previous
#include <cuda_runtime.h>
#include <cuda_fp16.h>
#include <mma.h>
#include <math.h>
#include <cstdint>

using namespace nvcuda;

#define Bsz   1024
#define Wsz   6
#define Dsz   512
#define Vsz   50257
#define Ksz   3072          // W*D
#define NSTEP 16

#define CUBIC_GAIN 0.032f
#define LAM   0.1f
#define SIG   0.5f
#define EPSN  1e-8f
#define ASYM_STR 1.25f
#define LN_EPS 1e-5f

// device-global scratch (no allocation allowed)
__device__ __align__(16) float  g_S[Bsz * Wsz * Dsz];
__device__ __align__(16) float  g_T[Bsz * Wsz * Dsz];
__device__ __align__(16) __half g_Sh[Bsz * Wsz * Dsz];      // fp16 mirror of S
__device__ __align__(16) __half g_Dh[Dsz * Dsz];            // fp16 diffusion
__device__ __align__(16) __half g_Bh[(size_t)Vsz * Ksz];    // fp16 readout

__device__ __forceinline__ float softplusf(float x) {
    return x > 0.f ? x + log1pf(expf(-x)) : log1pf(expf(x));
}

__device__ __forceinline__ void cp_async16h(__half* smem_dst, const __half* gmem_src,
                                            bool valid) {
    unsigned int saddr = (unsigned int)__cvta_generic_to_shared(smem_dst);
    int sz = valid ? 16 : 0;
    asm volatile("cp.async.ca.shared.global [%0], [%1], 16, %2;\n"
                 :: "r"(saddr), "l"(gmem_src), "r"(sz));
}

// ---------------------------------------------------------------------------
// gather + LayerNorm (writes fp32 state + fp16 mirror)
// ---------------------------------------------------------------------------
__global__ void gather_ln_kernel(const int* __restrict__ tokens,
                                 const float* __restrict__ embed) {
    int row = blockIdx.x;
    int tok = tokens[row];
    const float4* src = reinterpret_cast<const float4*>(embed + (size_t)tok * Dsz);
    float4 v = src[threadIdx.x];

    float s  = v.x + v.y + v.z + v.w;
    float sq = v.x * v.x + v.y * v.y + v.z * v.z + v.w * v.w;

    __shared__ float sh_s[4], sh_q[4];
    #pragma unroll
    for (int o = 16; o > 0; o >>= 1) {
        s  += __shfl_down_sync(0xFFFFFFFFu, s, o);
        sq += __shfl_down_sync(0xFFFFFFFFu, sq, o);
    }
    int wid = threadIdx.x >> 5, lane = threadIdx.x & 31;
    if (lane == 0) { sh_s[wid] = s; sh_q[wid] = sq; }
    __syncthreads();
    float fs = sh_s[0] + sh_s[1] + sh_s[2] + sh_s[3];
    float fq = sh_q[0] + sh_q[1] + sh_q[2] + sh_q[3];
    float mu  = fs * (1.f / Dsz);
    float var = fq * (1.f / Dsz) - mu * mu;
    float rstd = rsqrtf(var + LN_EPS);

    float4 o;
    o.x = (v.x - mu) * rstd;
    o.y = (v.y - mu) * rstd;
    o.z = (v.z - mu) * rstd;
    o.w = (v.w - mu) * rstd;
    reinterpret_cast<float4*>(g_S + (size_t)row * Dsz)[threadIdx.x] = o;

    __half2* hrow = reinterpret_cast<__half2*>(g_Sh + (size_t)row * Dsz);
    hrow[threadIdx.x * 2 + 0] = __floats2half2_rn(o.x, o.y);
    hrow[threadIdx.x * 2 + 1] = __floats2half2_rn(o.z, o.w);
}

// ---------------------------------------------------------------------------
// fp32 -> fp16 converters
// ---------------------------------------------------------------------------
__global__ void conv_w_kernel(const float* __restrict__ w) {
    size_t n4 = (size_t)Vsz * Ksz / 4;
    const float4* in = reinterpret_cast<const float4*>(w);
    uint2* o = reinterpret_cast<uint2*>(g_Bh);
    for (size_t i = (size_t)blockIdx.x * blockDim.x + threadIdx.x; i < n4;
         i += (size_t)gridDim.x * blockDim.x) {
        float4 v = in[i];
        __half2 lo = __floats2half2_rn(v.x, v.y);
        __half2 hi = __floats2half2_rn(v.z, v.w);
        uint2 pk;
        pk.x = *reinterpret_cast<unsigned*>(&lo);
        pk.y = *reinterpret_cast<unsigned*>(&hi);
        o[i] = pk;
    }
}

__global__ void conv_d_kernel(const float* __restrict__ dmat) {
    size_t n2 = (size_t)Dsz * Dsz / 2;
    const float2* in = reinterpret_cast<const float2*>(dmat);
    __half2* o = reinterpret_cast<__half2*>(g_Dh);
    for (size_t i = (size_t)blockIdx.x * blockDim.x + threadIdx.x; i < n2;
         i += (size_t)gridDim.x * blockDim.x)
        o[i] = __float22half2_rn(in[i]);
}

// ---------------------------------------------------------------------------
// STEP GEMM (proven R9): 64x64x64 tiles, 128 threads, 2-stage, 5 CTAs/SM.
// ---------------------------------------------------------------------------
#define SBM 64
#define SBN 64
#define SBK 64
#define SLDS (SBK + 8)
#define S_SMEM_BYTES (2 * (SBM + SBN) * SLDS * 2)   // 36864

__global__ __launch_bounds__(128, 5)
void gemm_step(const __half* __restrict__ A, const __half* __restrict__ Bmat,
               float* __restrict__ C, int M, int N, int K) {
    extern __shared__ __half smh[];
    __half* As = smh;
    __half* Bs = smh + 2 * SBM * SLDS;

    const int m0 = blockIdx.x * SBM;
    const int n0 = blockIdx.y * SBN;
    const int tid = threadIdx.x;
    const int warp = tid >> 5;
    const int wm = warp >> 1;
    const int wn = warp & 1;
    const int r_ld = tid >> 3;
    const int c_ld = (tid & 7) * 8;

    wmma::fragment<wmma::accumulator, 16, 16, 16, float> acc[2][2];
    #pragma unroll
    for (int mi = 0; mi < 2; mi++)
        #pragma unroll
        for (int ni = 0; ni < 2; ni++)
            wmma::fill_fragment(acc[mi][ni], 0.0f);

    const int niter = K / SBK;

    auto load_stage = [&](int st, int k0) {
        __half* as = As + st * SBM * SLDS;
        __half* bs = Bs + st * SBN * SLDS;
        #pragma unroll
        for (int t = 0; t < 4; t++) {
            int r = r_ld + t * 16;
            cp_async16h(as + r * SLDS + c_ld,
                        A + (size_t)(m0 + r) * K + k0 + c_ld, true);
        }
        #pragma unroll
        for (int t = 0; t < 4; t++) {
            int r = r_ld + t * 16;
            cp_async16h(bs + r * SLDS + c_ld,
                        Bmat + (size_t)(n0 + r) * K + k0 + c_ld, true);
        }
        asm volatile("cp.async.commit_group;\n" ::: "memory");
    };

    load_stage(0, 0);

    for (int i = 0; i < niter; i++) {
        if (i + 1 < niter) {
            load_stage((i + 1) & 1, (i + 1) * SBK);
            asm volatile("cp.async.wait_group 1;\n" ::: "memory");
        } else {
            asm volatile("cp.async.wait_group 0;\n" ::: "memory");
        }
        __syncthreads();

        const int st = i & 1;
        const __half* as = As + st * SBM * SLDS;
        const __half* bs = Bs + st * SBN * SLDS;

        #pragma unroll
        for (int ks = 0; ks < SBK; ks += 16) {
            wmma::fragment<wmma::matrix_a, 16, 16, 16, __half,
                           wmma::row_major> af[2];
            wmma::fragment<wmma::matrix_b, 16, 16, 16, __half,
                           wmma::col_major> bf[2];
            #pragma unroll
            for (int mi = 0; mi < 2; mi++)
                wmma::load_matrix_sync(af[mi],
                    as + (size_t)(wm * 32 + mi * 16) * SLDS + ks, SLDS);
            #pragma unroll
            for (int ni = 0; ni < 2; ni++)
                wmma::load_matrix_sync(bf[ni],
                    bs + (size_t)(wn * 32 + ni * 16) * SLDS + ks, SLDS);
            #pragma unroll
            for (int mi = 0; mi < 2; mi++)
                #pragma unroll
                for (int ni = 0; ni < 2; ni++)
                    wmma::mma_sync(acc[mi][ni], af[mi], bf[ni], acc[mi][ni]);
        }
        __syncthreads();
    }

    #pragma unroll
    for (int mi = 0; mi < 2; mi++)
        #pragma unroll
        for (int ni = 0; ni < 2; ni++) {
            size_t off = (size_t)(m0 + wm * 32 + mi * 16) * N
                       + (n0 + wn * 32 + ni * 16);
            wmma::store_matrix_sync(C + off, acc[mi][ni], N, wmma::mem_row_major);
        }
}

// ---------------------------------------------------------------------------
// FINAL GEMM (proven R12): 128x128x64, 128 threads, 4 warps (2x2, warp tile
// 64x64), 2-stage cp.async. smem 73728 B/CTA, 2 CTAs/SM.
// ---------------------------------------------------------------------------
#define GBM 128
#define GBN 128
#define GBK 64
#define GLDS (GBK + 8)                     // 72 halves (144 B) per row
#define GSTG_HALVES ((GBM + GBN) * GLDS)
#define GEMM_SMEM_BYTES (2 * GSTG_HALVES * 2)   // 73728

__global__ __launch_bounds__(128, 2)
void gemm_h(const __half* __restrict__ A, const __half* __restrict__ Bmat,
            float* __restrict__ C, int M, int N, int K) {
    extern __shared__ __half smh[];

    const int m0 = blockIdx.x * GBM;
    const int n0 = blockIdx.y * GBN;
    const int tid = threadIdx.x;
    const int warp = tid >> 5, lane = tid & 31;
    const int wm = warp >> 1;            // 0..1 (64-row half)
    const int wn = warp & 1;             // 0..1 (64-col half)
    const int r_ld = tid >> 3;           // 0..15
    const int c_ld = (tid & 7) * 8;      // 0..56 halves

    wmma::fragment<wmma::accumulator, 16, 16, 16, float> acc[4][4];
    #pragma unroll
    for (int mi = 0; mi < 4; mi++)
        #pragma unroll
        for (int ni = 0; ni < 4; ni++)
            wmma::fill_fragment(acc[mi][ni], 0.0f);

    const int niter = K / GBK;      // 48

    auto load_stage = [&](int st, int k0) {
        __half* as = smh + st * GSTG_HALVES;
        __half* bs = as + GBM * GLDS;
        #pragma unroll
        for (int t = 0; t < 8; t++) {
            int r = r_ld + t * 16;
            cp_async16h(as + r * GLDS + c_ld,
                        A + (size_t)(m0 + r) * K + k0 + c_ld, true);
        }
        #pragma unroll
        for (int t = 0; t < 8; t++) {
            int r = r_ld + t * 16;
            int n = n0 + r;
            bool v = (n < N);
            cp_async16h(bs + r * GLDS + c_ld,
                        Bmat + (size_t)(v ? n : 0) * K + k0 + c_ld, v);
        }
        asm volatile("cp.async.commit_group;\n" ::: "memory");
    };

    load_stage(0, 0);

    for (int i = 0; i < niter; i++) {
        if (i + 1 < niter) {
            load_stage((i + 1) & 1, (i + 1) * GBK);
            asm volatile("cp.async.wait_group 1;\n" ::: "memory");
        } else {
            asm volatile("cp.async.wait_group 0;\n" ::: "memory");
        }
        __syncthreads();

        const int st = i & 1;
        const __half* as = smh + st * GSTG_HALVES;
        const __half* bs = as + GBM * GLDS;

        #pragma unroll
        for (int ks = 0; ks < GBK; ks += 16) {
            wmma::fragment<wmma::matrix_a, 16, 16, 16, __half,
                           wmma::row_major> af[4];
            wmma::fragment<wmma::matrix_b, 16, 16, 16, __half,
                           wmma::col_major> bf[4];
            #pragma unroll
            for (int mi = 0; mi < 4; mi++)
                wmma::load_matrix_sync(af[mi],
                    as + (size_t)(wm * 64 + mi * 16) * GLDS + ks, GLDS);
            #pragma unroll
            for (int ni = 0; ni < 4; ni++)
                wmma::load_matrix_sync(bf[ni],
                    bs + (size_t)(wn * 64 + ni * 16) * GLDS + ks, GLDS);
            #pragma unroll
            for (int mi = 0; mi < 4; mi++)
                #pragma unroll
                for (int ni = 0; ni < 4; ni++)
                    wmma::mma_sync(acc[mi][ni], af[mi], bf[ni], acc[mi][ni]);
        }
        __syncthreads();
    }

    if (((N & 3) == 0) && (n0 + GBN <= N)) {
        #pragma unroll
        for (int mi = 0; mi < 4; mi++)
            #pragma unroll
            for (int ni = 0; ni < 4; ni++) {
                size_t off = (size_t)(m0 + wm * 64 + mi * 16) * N
                           + (n0 + wn * 64 + ni * 16);
                wmma::store_matrix_sync(C + off, acc[mi][ni], N,
                                        wmma::mem_row_major);
            }
    } else {
        float* wbuf = reinterpret_cast<float*>(smh) + warp * 256;
        #pragma unroll
        for (int mi = 0; mi < 4; mi++) {
            #pragma unroll
            for (int ni = 0; ni < 4; ni++) {
                wmma::store_matrix_sync(wbuf, acc[mi][ni], 16,
                                        wmma::mem_row_major);
                __syncwarp();
                int mrow0 = m0 + wm * 64 + mi * 16;
                int ncol0 = n0 + wn * 64 + ni * 16;
                #pragma unroll
                for (int e = lane; e < 256; e += 32) {
                    int rr = e >> 4, cc = e & 15;
                    int n = ncol0 + cc;
                    if (n < N)
                        C[(size_t)(mrow0 + rr) * N + n] = wbuf[e];
                }
                __syncwarp();
            }
        }
    }
}

// ---------------------------------------------------------------------------
// fused update kernel (writes fp32 state + fp16 mirror)
// ---------------------------------------------------------------------------
__device__ __forceinline__ void block_reduce6(float v[Wsz], float red[Wsz][16],
                                              int wid, int lane) {
    #pragma unroll
    for (int i = 0; i < Wsz; i++) {
        float x = v[i];
        #pragma unroll
        for (int o = 16; o > 0; o >>= 1)
            x += __shfl_down_sync(0xFFFFFFFFu, x, o);
        if (lane == 0) red[i][wid] = x;
    }
    __syncthreads();
    #pragma unroll
    for (int i = 0; i < Wsz; i++) {
        float t = 0.f;
        #pragma unroll
        for (int w = 0; w < 16; w++) t += red[i][w];
        v[i] = t;
    }
    __syncthreads();
}

__global__ __launch_bounds__(512)
void update_kernel(const float* __restrict__ beta_p,
                   const float* __restrict__ gamma_raw,
                   const float* __restrict__ scale_raw,
                   const float* __restrict__ dt_raw,
                   const float* __restrict__ asym_p) {
    int b = blockIdx.x;
    int d = threadIdx.x;
    int wid = d >> 5, lane = d & 31;

    __shared__ float Wsh[Wsz][Wsz];
    __shared__ float wsumsh[Wsz];
    __shared__ float red[Wsz][16];

    float gamma = softplusf(*gamma_raw);
    float scale = softplusf(*scale_raw);
    float dt    = softplusf(*dt_raw);
    float beta  = *beta_p;
    float ta    = tanhf(*asym_p);
    float coeff = beta * SIG * scale;

    if (d < Wsz * Wsz) {
        int i = d / Wsz, j = d % Wsz;
        float w = 0.f;
        if (i != j) {
            float ji = (float)(j - i);
            float sgn = (ji > 0.f) ? 1.f : -1.f;
            float af = fmaxf(1.f + ASYM_STR * ta * sgn, 0.2f);
            w = expf(-gamma * fabsf(ji)) * af * coeff;
        }
        Wsh[i][j] = w;
    }
    __syncthreads();
    if (d < Wsz) {
        float ws = 0.f;
        #pragma unroll
        for (int j = 0; j < Wsz; j++) ws += Wsh[d][j];
        wsumsh[d] = ws;
    }
    __syncthreads();

    size_t base = (size_t)b * Wsz * Dsz + d;
    float s_loc[Wsz], t_loc[Wsz];
    #pragma unroll
    for (int i = 0; i < Wsz; i++) {
        s_loc[i] = g_S[base + i * Dsz];
        t_loc[i] = g_T[base + i * Dsz];
    }

    float mu[Wsz];
    #pragma unroll
    for (int i = 0; i < Wsz; i++) mu[i] = s_loc[i];
    block_reduce6(mu, red, wid, lane);
    #pragma unroll
    for (int i = 0; i < Wsz; i++) mu[i] *= (1.f / Dsz);

    float sn[Wsz], sq[Wsz];
    #pragma unroll
    for (int i = 0; i < Wsz; i++) {
        float sig = -wsumsh[i] * s_loc[i];
        #pragma unroll
        for (int j = 0; j < Wsz; j++)
            sig = fmaf(Wsh[i][j], s_loc[j], sig);
        float c = s_loc[i] - mu[i];
        float drift = t_loc[i] + CUBIC_GAIN * tanhf(c) + sig - LAM * s_loc[i];
        float v = fmaf(dt, drift, s_loc[i]);
        if (!isfinite(v)) v = 0.f;
        sn[i] = v;
        sq[i] = v * v;
    }

    block_reduce6(sq, red, wid, lane);

    #pragma unroll
    for (int i = 0; i < Wsz; i++) {
        float nrm = sqrtf(sq[i]);
        float o = sn[i] / (nrm + EPSN);
        o = fminf(fmaxf(o, -10.f), 10.f);
        g_S[base + i * Dsz]  = o;
        g_Sh[base + i * Dsz] = __float2half_rn(o);
    }
}

// ---------------------------------------------------------------------------
// launch: conv_w forked onto a side stream, overlapped with the step loop.
// ---------------------------------------------------------------------------
extern "C" void kernel_launch(void* const* d_in, const int* in_sizes, int n_in,
                              void* d_out, int out_size) {
    const int*   tokens    = (const int*)d_in[0];
    const float* embed     = (const float*)d_in[1];
    const float* diffusion = (const float*)d_in[2];
    const float* readout   = (const float*)d_in[3];
    const float* beta      = (const float*)d_in[4];
    const float* g_raw     = (const float*)d_in[5];
    const float* s_raw     = (const float*)d_in[6];
    const float* dtraw     = (const float*)d_in[7];
    const float* asym      = (const float*)d_in[8];
    float* out = (float*)d_out;

    cudaFuncSetAttribute(gemm_h,
                         cudaFuncAttributeMaxDynamicSharedMemorySize,
                         GEMM_SMEM_BYTES);
    cudaFuncSetAttribute(gemm_step,
                         cudaFuncAttributeMaxDynamicSharedMemorySize,
                         S_SMEM_BYTES);

    void* sh_p;  cudaGetSymbolAddress(&sh_p, g_Sh);
    void* dh_p;  cudaGetSymbolAddress(&dh_p, g_Dh);
    void* bh_p;  cudaGetSymbolAddress(&bh_p, g_Bh);
    void* t_p;   cudaGetSymbolAddress(&t_p,  g_T);
    const __half* Sh = (const __half*)sh_p;
    const __half* Dh = (const __half*)dh_p;
    const __half* Bh = (const __half*)bh_p;
    float* Tp = (float*)t_p;

    cudaStream_t s2;
    cudaStreamCreateWithFlags(&s2, cudaStreamNonBlocking);
    cudaEvent_t eFork, eJoin;
    cudaEventCreateWithFlags(&eFork, cudaEventDisableTiming);
    cudaEventCreateWithFlags(&eJoin, cudaEventDisableTiming);

    cudaEventRecord(eFork, 0);
    cudaStreamWaitEvent(s2, eFork, 0);
    conv_w_kernel<<<8192, 256, 0, s2>>>(readout);
    cudaEventRecord(eJoin, s2);

    conv_d_kernel<<<256, 256>>>(diffusion);
    gather_ln_kernel<<<Bsz * Wsz, 128>>>(tokens, embed);

    for (int s = 0; s < NSTEP; s++) {
        gemm_step<<<dim3((Bsz * Wsz) / SBM, Dsz / SBN), 128, S_SMEM_BYTES>>>(
            Sh, Dh, Tp, Bsz * Wsz, Dsz, Dsz);
        update_kernel<<<Bsz, Dsz>>>(beta, g_raw, s_raw, dtraw, asym);
    }

    cudaStreamWaitEvent(0, eJoin, 0);

    // logits = S.reshape(1024, 3072) @ readout^T  (M=1024, N=50257, K=3072)
    gemm_h<<<dim3(Bsz / GBM, (Vsz + GBN - 1) / GBN), 128, GEMM_SMEM_BYTES>>>(
        Sh, Bh, out, Bsz, Vsz, Ksz);
}